// round 2
// baseline (speedup 1.0000x reference)
#include <cuda_runtime.h>

// VectorQuantizer: x [8,4,32,32] f32, codebook [16384,4] f32
// Outputs concatenated into d_out (f32):
//   [0 .. 32767]   embed_st transposed back to [8,4,32,32] (== gathered codebook rows)
//   [32768]        loss = 1.25 * mean((embed - z)^2)
//   [32769..40960] idx (argmin codes, cast to float)

#define FMUL __fmul_rn
#define FADD __fadd_rn
#define FFMA __fmaf_rn

constexpr int N_PTS   = 8192;          // 8 * 32 * 32
constexpr int K_CODES = 16384;
constexpr int KSPLIT  = 16;
constexpr int KCHUNK  = K_CODES / KSPLIT;   // 1024
constexpr int THREADS = 128;
constexpr int PPT     = 4;                  // points per thread
constexpr int PPB     = THREADS * PPT;      // 512 points per block
constexpr int PGROUPS = N_PTS / PPB;        // 16

// Scratch (no allocations allowed -> __device__ globals)
__device__ float  g_pdist[KSPLIT * N_PTS];
__device__ int    g_pidx [KSPLIT * N_PTS];
__device__ double g_loss;

__global__ void vq_init_kernel() { g_loss = 0.0; }

__global__ __launch_bounds__(THREADS)
void vq_dist_kernel(const float* __restrict__ x, const float4* __restrict__ cb) {
    __shared__ float4 se [KCHUNK];
    __shared__ float  se2[KCHUNK];

    const int ks = blockIdx.x;   // K-split   0..15
    const int pg = blockIdx.y;   // point grp 0..15
    const int k0 = ks * KCHUNK;

    // Stage codebook chunk + precompute ||e||^2 with reference's op order
    for (int i = threadIdx.x; i < KCHUNK; i += THREADS) {
        float4 e = cb[k0 + i];
        se[i]  = e;
        se2[i] = FADD(FADD(FADD(FMUL(e.x, e.x), FMUL(e.y, e.y)),
                           FMUL(e.z, e.z)), FMUL(e.w, e.w));
    }
    __syncthreads();

    float zx[PPT], zy[PPT], zz[PPT], zw[PPT], z2[PPT], best[PPT];
    int   bidx[PPT];

    #pragma unroll
    for (int j = 0; j < PPT; j++) {
        int n  = pg * PPB + j * THREADS + threadIdx.x;
        int b  = n >> 10;
        int hw = n & 1023;
        const float* xp = x + b * 4096 + hw;    // x[b][c][h][w], c stride = 1024
        zx[j] = xp[0];
        zy[j] = xp[1024];
        zz[j] = xp[2048];
        zw[j] = xp[3072];
        z2[j] = FADD(FADD(FADD(FMUL(zx[j], zx[j]), FMUL(zy[j], zy[j])),
                          FMUL(zz[j], zz[j])), FMUL(zw[j], zw[j]));
        best[j] = 3.4e38f;
        bidx[j] = 0;
    }

    #pragma unroll 4
    for (int k = 0; k < KCHUNK; k++) {
        float4 e   = se[k];      // broadcast load: all lanes same address
        float  e2k = se2[k];
        #pragma unroll
        for (int j = 0; j < PPT; j++) {
            // dot = fma-chain ascending in component, matching gemm accumulation
            float dot = FFMA(zw[j], e.w,
                        FFMA(zz[j], e.z,
                        FFMA(zy[j], e.y,
                        FMUL(zx[j], e.x))));
            // d = fl( fl(z2 + e2) - 2*dot )   (2*dot exact; fma = single rounding)
            float d = FFMA(-2.0f, dot, FADD(z2[j], e2k));
            if (d < best[j]) { best[j] = d; bidx[j] = k0 + k; }  // first-min tiebreak
        }
    }

    #pragma unroll
    for (int j = 0; j < PPT; j++) {
        int n = pg * PPB + j * THREADS + threadIdx.x;
        g_pdist[ks * N_PTS + n] = best[j];
        g_pidx [ks * N_PTS + n] = bidx[j];
    }
}

__global__ __launch_bounds__(256)
void vq_reduce_kernel(const float* __restrict__ x, const float4* __restrict__ cb,
                      float* __restrict__ out) {
    int n = blockIdx.x * blockDim.x + threadIdx.x;   // 0..8191

    float best = g_pdist[n];
    int   bi   = g_pidx [n];
    #pragma unroll
    for (int s = 1; s < KSPLIT; s++) {
        float d = g_pdist[s * N_PTS + n];
        if (d < best) { best = d; bi = g_pidx[s * N_PTS + n]; }  // ascending splits: first-min
    }

    float4 e = cb[bi];

    int b  = n >> 10;
    int hw = n & 1023;
    float*       op = out + b * 4096 + hw;
    const float* xp = x   + b * 4096 + hw;

    op[0]    = e.x;
    op[1024] = e.y;
    op[2048] = e.z;
    op[3072] = e.w;

    out[32768 + 1 + n] = (float)bi;

    float dx = e.x - xp[0];
    float dy = e.y - xp[1024];
    float dz = e.z - xp[2048];
    float dw = e.w - xp[3072];
    float ls = dx * dx + dy * dy + dz * dz + dw * dw;

    #pragma unroll
    for (int o = 16; o > 0; o >>= 1)
        ls += __shfl_down_sync(0xffffffffu, ls, o);
    if ((threadIdx.x & 31) == 0)
        atomicAdd(&g_loss, (double)ls);
}

__global__ void vq_loss_kernel(float* __restrict__ out) {
    // loss = mean((embed-z)^2) + 0.25 * mean((embed-z)^2) = 1.25 * sum / 32768
    out[32768] = (float)(g_loss * (1.25 / 32768.0));
}

extern "C" void kernel_launch(void* const* d_in, const int* in_sizes, int n_in,
                              void* d_out, int out_size) {
    const float*  x   = (const float*)d_in[0];
    const float4* cb  = (const float4*)d_in[1];
    float*        out = (float*)d_out;

    vq_init_kernel<<<1, 1>>>();
    vq_dist_kernel<<<dim3(KSPLIT, PGROUPS), THREADS>>>(x, cb);
    vq_reduce_kernel<<<N_PTS / 256, 256>>>(x, cb, out);
    vq_loss_kernel<<<1, 1>>>(out);
}

// round 4
// speedup vs baseline: 1.2222x; 1.2222x over previous
#include <cuda_runtime.h>

// VectorQuantizer: x [8,4,32,32] f32, codebook [16384,4] f32
// d_out (f32): [0..32767] embed_st [8,4,32,32]; [32768] loss; [32769..40960] idx

#define FMUL __fmul_rn
#define FADD __fadd_rn
#define FFMA __fmaf_rn

typedef unsigned long long u64;

constexpr int N_PTS   = 8192;
constexpr int K_CODES = 16384;
constexpr int KSPLIT  = 32;
constexpr int KCHUNK  = K_CODES / KSPLIT;   // 512
constexpr int K2      = KCHUNK / 2;         // 256 packed code-pairs
constexpr int THREADS = 128;
constexpr int PPT     = 4;
constexpr int PPB     = THREADS * PPT;      // 512
constexpr int PGROUPS = N_PTS / PPB;        // 16
constexpr int SUB     = 8;                  // codes per argmin sub-block
constexpr int RBLK    = 256;                // reduce kernel block size
constexpr int NRB     = N_PTS / RBLK;       // 32

// Scratch (__device__ globals: no allocations allowed)
__device__ float g_pdist[KSPLIT * N_PTS];
__device__ int   g_pbst [KSPLIT * N_PTS];   // sub-block start code index
__device__ float g_lsum [NRB];

// ---------- f32x2 packed helpers (bit-exact per lane) ----------
__device__ __forceinline__ u64 pk(float lo, float hi) {
    u64 r; asm("mov.b64 %0, {%1,%2};" : "=l"(r) : "f"(lo), "f"(hi)); return r;
}
__device__ __forceinline__ void upk(float& lo, float& hi, u64 v) {
    asm("mov.b64 {%0,%1}, %2;" : "=f"(lo), "=f"(hi) : "l"(v));
}
__device__ __forceinline__ u64 mul2(u64 a, u64 b) {
    u64 d; asm("mul.rn.f32x2 %0, %1, %2;" : "=l"(d) : "l"(a), "l"(b)); return d;
}
__device__ __forceinline__ u64 add2(u64 a, u64 b) {
    u64 d; asm("add.rn.f32x2 %0, %1, %2;" : "=l"(d) : "l"(a), "l"(b)); return d;
}
__device__ __forceinline__ u64 fma2(u64 a, u64 b, u64 c) {
    u64 d; asm("fma.rn.f32x2 %0, %1, %2, %3;" : "=l"(d) : "l"(a), "l"(b), "l"(c)); return d;
}

__device__ __forceinline__ float e2_of(float4 e) {
    return FADD(FADD(FADD(FMUL(e.x, e.x), FMUL(e.y, e.y)),
                     FMUL(e.z, e.z)), FMUL(e.w, e.w));
}

// ---------- distance kernel: per (ksplit, pointgroup), sub-block argmin ----------
__global__ __launch_bounds__(THREADS)
void vq_dist_kernel(const float* __restrict__ x, const float4* __restrict__ cb) {
    __shared__ ulonglong2 sAB[K2];   // {ex-pair, ey-pair}
    __shared__ ulonglong2 sCD[K2];   // {ez-pair, ew-pair}
    __shared__ u64        sE2[K2];   // {e2-pair}

    const int ks = blockIdx.x;
    const int pg = blockIdx.y;
    const int k0 = ks * KCHUNK;

    for (int i = threadIdx.x; i < K2; i += THREADS) {
        float4 e0 = cb[k0 + 2 * i];
        float4 e1 = cb[k0 + 2 * i + 1];
        sAB[i] = make_ulonglong2(pk(e0.x, e1.x), pk(e0.y, e1.y));
        sCD[i] = make_ulonglong2(pk(e0.z, e1.z), pk(e0.w, e1.w));
        sE2[i] = pk(e2_of(e0), e2_of(e1));
    }
    __syncthreads();

    u64 zx2[PPT], zy2[PPT], zz2[PPT], zw2[PPT], z2p[PPT];
    float best[PPT];
    int   bst [PPT];

    #pragma unroll
    for (int j = 0; j < PPT; j++) {
        int n  = pg * PPB + j * THREADS + threadIdx.x;
        int b  = n >> 10;
        int hw = n & 1023;
        const float* xp = x + b * 4096 + hw;     // c stride = 1024
        float zx = xp[0], zy = xp[1024], zz = xp[2048], zw = xp[3072];
        float z2 = FADD(FADD(FADD(FMUL(zx, zx), FMUL(zy, zy)),
                             FMUL(zz, zz)), FMUL(zw, zw));
        zx2[j] = pk(zx, zx); zy2[j] = pk(zy, zy);
        zz2[j] = pk(zz, zz); zw2[j] = pk(zw, zw);
        z2p[j] = pk(z2, z2);
        best[j] = 3.4e38f;
        bst [j] = k0;
    }

    const u64 NEG2 = pk(-2.0f, -2.0f);

    #pragma unroll 2
    for (int sb = 0; sb < K2; sb += SUB / 2) {     // 4 packed steps = 8 codes
        float m[PPT];
        #pragma unroll
        for (int j = 0; j < PPT; j++) m[j] = 3.4e38f;

        #pragma unroll
        for (int t = 0; t < SUB / 2; t++) {
            ulonglong2 ab = sAB[sb + t];
            ulonglong2 cd = sCD[sb + t];
            u64 e2p = sE2[sb + t];
            #pragma unroll
            for (int j = 0; j < PPT; j++) {
                u64 dot = fma2(zw2[j], cd.y,
                          fma2(zz2[j], cd.x,
                          fma2(zy2[j], ab.y,
                          mul2(zx2[j], ab.x))));
                u64 d2 = fma2(NEG2, dot, add2(z2p[j], e2p));
                float d0, d1; upk(d0, d1, d2);
                m[j] = fminf(m[j], fminf(d0, d1));
            }
        }
        #pragma unroll
        for (int j = 0; j < PPT; j++)
            if (m[j] < best[j]) { best[j] = m[j]; bst[j] = k0 + 2 * sb; }
    }

    #pragma unroll
    for (int j = 0; j < PPT; j++) {
        int n = pg * PPB + j * THREADS + threadIdx.x;
        g_pdist[ks * N_PTS + n] = best[j];
        g_pbst [ks * N_PTS + n] = bst[j];
    }
}

// ---------- reduce: combine splits, resolve exact index, write outputs ----------
__global__ __launch_bounds__(RBLK)
void vq_reduce_kernel(const float* __restrict__ x, const float4* __restrict__ cb,
                      float* __restrict__ out) {
    int n = blockIdx.x * RBLK + threadIdx.x;

    float best = g_pdist[n];
    int   bs   = g_pbst [n];
    #pragma unroll
    for (int s = 1; s < KSPLIT; s++) {
        float d = g_pdist[s * N_PTS + n];
        if (d < best) { best = d; bs = g_pbst[s * N_PTS + n]; }  // ascending: first-min
    }

    int b  = n >> 10;
    int hw = n & 1023;
    const float* xp = x + b * 4096 + hw;
    float zx = xp[0], zy = xp[1024], zz = xp[2048], zw = xp[3072];
    float z2 = FADD(FADD(FADD(FMUL(zx, zx), FMUL(zy, zy)),
                         FMUL(zz, zz)), FMUL(zw, zw));

    // Re-scan the 8-code winning sub-block; first k with d == best (exact ops)
    int bi = bs;
    bool found = false;
    float4 eb = cb[bs];
    #pragma unroll
    for (int t = 0; t < SUB; t++) {
        float4 e = cb[bs + t];
        float dot = FFMA(zw, e.w, FFMA(zz, e.z, FFMA(zy, e.y, FMUL(zx, e.x))));
        float d   = FFMA(-2.0f, dot, FADD(z2, e2_of(e)));
        if (!found && d == best) { bi = bs + t; eb = e; found = true; }
    }

    float* op = out + b * 4096 + hw;
    op[0]    = eb.x;
    op[1024] = eb.y;
    op[2048] = eb.z;
    op[3072] = eb.w;
    out[32768 + 1 + n] = (float)bi;

    float dx = eb.x - zx, dy = eb.y - zy, dz = eb.z - zz, dw = eb.w - zw;
    float ls = dx * dx + dy * dy + dz * dz + dw * dw;

    #pragma unroll
    for (int o = 16; o > 0; o >>= 1)
        ls += __shfl_down_sync(0xffffffffu, ls, o);

    __shared__ float wsum[RBLK / 32];
    if ((threadIdx.x & 31) == 0) wsum[threadIdx.x >> 5] = ls;
    __syncthreads();
    if (threadIdx.x == 0) {
        float s = 0.0f;
        #pragma unroll
        for (int w = 0; w < RBLK / 32; w++) s += wsum[w];
        g_lsum[blockIdx.x] = s;     // deterministic
    }
}

__global__ void vq_loss_kernel(float* __restrict__ out) {
    double s = 0.0;
    #pragma unroll
    for (int i = 0; i < NRB; i++) s += (double)g_lsum[i];
    out[32768] = (float)(s * (1.25 / 32768.0));   // (1 + 0.25) * mean
}

extern "C" void kernel_launch(void* const* d_in, const int* in_sizes, int n_in,
                              void* d_out, int out_size) {
    const float*  x   = (const float*)d_in[0];
    const float4* cb  = (const float4*)d_in[1];
    float*        out = (float*)d_out;

    vq_dist_kernel<<<dim3(KSPLIT, PGROUPS), THREADS>>>(x, cb);
    vq_reduce_kernel<<<NRB, RBLK>>>(x, cb, out);
    vq_loss_kernel<<<1, 1>>>(out);
}

// round 6
// speedup vs baseline: 1.5091x; 1.2348x over previous
#include <cuda_runtime.h>

// VectorQuantizer: x [8,4,32,32] f32, codebook [16384,4] f32
// d_out (f32): [0..32767] embed_st [8,4,32,32]; [32768] loss; [32769..40960] idx

#define FMUL __fmul_rn
#define FADD __fadd_rn
#define FFMA __fmaf_rn

typedef unsigned long long u64;
typedef unsigned int u32;

constexpr int N_PTS   = 8192;
constexpr int K_CODES = 16384;
constexpr int KSPLIT  = 64;
constexpr int KCHUNK  = K_CODES / KSPLIT;   // 256
constexpr int K2      = KCHUNK / 2;         // 128 packed code-pairs
constexpr int THREADS = 128;
constexpr int PPT     = 4;
constexpr int PPB     = THREADS * PPT;      // 512
constexpr int PGROUPS = N_PTS / PPB;        // 16
constexpr int SUB     = 8;                  // codes per argmin sub-block
constexpr int RBLK    = 256;
constexpr int NRB     = N_PTS / RBLK;       // 32

// Scratch (__device__ globals: no allocations allowed)
__device__ u64      g_key [KSPLIT * N_PTS];   // (orderable dist bits << 32) | sub-block start
__device__ float    g_lsum[NRB];
__device__ unsigned g_ctr = 0;

// ---------- f32x2 packed helpers (bit-exact per lane) ----------
__device__ __forceinline__ u64 pk(float lo, float hi) {
    u64 r; asm("mov.b64 %0, {%1,%2};" : "=l"(r) : "f"(lo), "f"(hi)); return r;
}
__device__ __forceinline__ void upk(float& lo, float& hi, u64 v) {
    asm("mov.b64 {%0,%1}, %2;" : "=f"(lo), "=f"(hi) : "l"(v));
}
__device__ __forceinline__ u64 mul2(u64 a, u64 b) {
    u64 d; asm("mul.rn.f32x2 %0, %1, %2;" : "=l"(d) : "l"(a), "l"(b)); return d;
}
__device__ __forceinline__ u64 add2(u64 a, u64 b) {
    u64 d; asm("add.rn.f32x2 %0, %1, %2;" : "=l"(d) : "l"(a), "l"(b)); return d;
}
__device__ __forceinline__ u64 fma2(u64 a, u64 b, u64 c) {
    u64 d; asm("fma.rn.f32x2 %0, %1, %2, %3;" : "=l"(d) : "l"(a), "l"(b), "l"(c)); return d;
}

__device__ __forceinline__ float e2_of(float4 e) {
    return FADD(FADD(FADD(FMUL(e.x, e.x), FMUL(e.y, e.y)),
                     FMUL(e.z, e.z)), FMUL(e.w, e.w));
}

// Monotone float -> u32 (total order incl. negatives): key ordering == value ordering
__device__ __forceinline__ u32 f2key(float f) {
    u32 b = __float_as_uint(f);
    return (b & 0x80000000u) ? ~b : (b | 0x80000000u);
}
__device__ __forceinline__ float key2f(u32 k) {
    u32 b = (k & 0x80000000u) ? (k & 0x7FFFFFFFu) : ~k;
    return __uint_as_float(b);
}

// ---------- distance kernel ----------
__global__ __launch_bounds__(THREADS)
void vq_dist_kernel(const float* __restrict__ x, const float4* __restrict__ cb) {
    __shared__ ulonglong2 sAB[K2];   // {ex-pair, ey-pair}
    __shared__ ulonglong2 sCD[K2];   // {ez-pair, ew-pair}
    __shared__ u64        sE2[K2];

    const int ks = blockIdx.x;   // 0..63
    const int pg = blockIdx.y;   // 0..15
    const int k0 = ks * KCHUNK;

    {
        int i = threadIdx.x;     // exactly K2 == THREADS
        float4 e0 = cb[k0 + 2 * i];
        float4 e1 = cb[k0 + 2 * i + 1];
        sAB[i] = make_ulonglong2(pk(e0.x, e1.x), pk(e0.y, e1.y));
        sCD[i] = make_ulonglong2(pk(e0.z, e1.z), pk(e0.w, e1.w));
        sE2[i] = pk(e2_of(e0), e2_of(e1));
    }
    __syncthreads();

    u64 zx2[PPT], zy2[PPT], zz2[PPT], zw2[PPT], z2p[PPT];
    float best[PPT];
    int   bst [PPT];

    #pragma unroll
    for (int j = 0; j < PPT; j++) {
        int n  = pg * PPB + j * THREADS + threadIdx.x;
        int b  = n >> 10;
        int hw = n & 1023;
        const float* xp = x + b * 4096 + hw;
        float zx = xp[0], zy = xp[1024], zz = xp[2048], zw = xp[3072];
        float z2 = FADD(FADD(FADD(FMUL(zx, zx), FMUL(zy, zy)),
                             FMUL(zz, zz)), FMUL(zw, zw));
        zx2[j] = pk(zx, zx); zy2[j] = pk(zy, zy);
        zz2[j] = pk(zz, zz); zw2[j] = pk(zw, zw);
        z2p[j] = pk(z2, z2);
        best[j] = 3.4e38f;
        bst [j] = k0;
    }

    const u64 NEG2 = pk(-2.0f, -2.0f);

    #pragma unroll 4
    for (int sb = 0; sb < K2; sb += SUB / 2) {     // 4 packed steps = 8 codes
        float m[PPT];
        #pragma unroll
        for (int j = 0; j < PPT; j++) m[j] = 3.4e38f;

        #pragma unroll
        for (int t = 0; t < SUB / 2; t++) {
            ulonglong2 ab = sAB[sb + t];
            ulonglong2 cd = sCD[sb + t];
            u64 e2p = sE2[sb + t];
            #pragma unroll
            for (int j = 0; j < PPT; j++) {
                u64 dot = fma2(zw2[j], cd.y,
                          fma2(zz2[j], cd.x,
                          fma2(zy2[j], ab.y,
                          mul2(zx2[j], ab.x))));
                u64 d2 = fma2(NEG2, dot, add2(z2p[j], e2p));
                float d0, d1; upk(d0, d1, d2);
                m[j] = fminf(m[j], fminf(d0, d1));
            }
        }
        #pragma unroll
        for (int j = 0; j < PPT; j++)
            if (m[j] < best[j]) { best[j] = m[j]; bst[j] = k0 + 2 * sb; }
    }

    #pragma unroll
    for (int j = 0; j < PPT; j++) {
        int n = pg * PPB + j * THREADS + threadIdx.x;
        g_key[ks * N_PTS + n] = ((u64)f2key(best[j]) << 32) | (u32)bst[j];
    }
}

// ---------- reduce: key-min across splits, exact idx, outputs + fused loss ----------
__global__ __launch_bounds__(RBLK)
void vq_reduce_kernel(const float* __restrict__ x, const float4* __restrict__ cb,
                      float* __restrict__ out) {
    int n = blockIdx.x * RBLK + threadIdx.x;

    // min key == min dist, ties -> lowest sub-block start (== first occurrence)
    u64 bk = g_key[n];
    #pragma unroll
    for (int s = 1; s < KSPLIT; s++) {
        u64 k = g_key[s * N_PTS + n];
        bk = (k < bk) ? k : bk;
    }
    float best = key2f((u32)(bk >> 32));
    int   bs   = (int)(u32)(bk & 0xFFFFFFFFu);

    int b  = n >> 10;
    int hw = n & 1023;
    const float* xp = x + b * 4096 + hw;
    float zx = xp[0], zy = xp[1024], zz = xp[2048], zw = xp[3072];
    float z2 = FADD(FADD(FADD(FMUL(zx, zx), FMUL(zy, zy)),
                         FMUL(zz, zz)), FMUL(zw, zw));

    // Re-scan the 8-code winning sub-block; first k with d == best (exact ops)
    int bi = bs;
    bool found = false;
    float4 eb = cb[bs];
    #pragma unroll
    for (int t = 0; t < SUB; t++) {
        float4 e = cb[bs + t];
        float dot = FFMA(zw, e.w, FFMA(zz, e.z, FFMA(zy, e.y, FMUL(zx, e.x))));
        float d   = FFMA(-2.0f, dot, FADD(z2, e2_of(e)));
        if (!found && d == best) { bi = bs + t; eb = e; found = true; }
    }

    float* op = out + b * 4096 + hw;
    op[0]    = eb.x;
    op[1024] = eb.y;
    op[2048] = eb.z;
    op[3072] = eb.w;
    out[32768 + 1 + n] = (float)bi;

    float dx = eb.x - zx, dy = eb.y - zy, dz = eb.z - zz, dw = eb.w - zw;
    float ls = dx * dx + dy * dy + dz * dz + dw * dw;

    #pragma unroll
    for (int o = 16; o > 0; o >>= 1)
        ls += __shfl_down_sync(0xffffffffu, ls, o);

    __shared__ float wsum[RBLK / 32];
    if ((threadIdx.x & 31) == 0) wsum[threadIdx.x >> 5] = ls;
    __syncthreads();
    if (threadIdx.x == 0) {
        float s = 0.0f;
        #pragma unroll
        for (int w = 0; w < RBLK / 32; w++) s += wsum[w];
        g_lsum[blockIdx.x] = s;
        __threadfence();
        unsigned old = atomicAdd(&g_ctr, 1u);
        if (old == NRB - 1) {                 // last block finalizes loss
            double acc = 0.0;
            #pragma unroll
            for (int i = 0; i < NRB; i++) acc += (double)g_lsum[i];
            out[32768] = (float)(acc * (1.25 / 32768.0));   // (1+0.25)*mean
            g_ctr = 0;                        // self-reset for graph replay
        }
    }
}

extern "C" void kernel_launch(void* const* d_in, const int* in_sizes, int n_in,
                              void* d_out, int out_size) {
    const float*  x   = (const float*)d_in[0];
    const float4* cb  = (const float4*)d_in[1];
    float*        out = (float*)d_out;

    vq_dist_kernel<<<dim3(KSPLIT, PGROUPS), THREADS>>>(x, cb);
    vq_reduce_kernel<<<NRB, RBLK>>>(x, cb, out);
}